// round 5
// baseline (speedup 1.0000x reference)
#include <cuda_runtime.h>
#include <math.h>

#define B_   1024
#define D_   768
#define E_   1536
#define C_   150
#define P_   64
#define CPAD 160
#define NC_  151

// ------------------------- static device scratch -------------------------
__device__ float g_xh[B_ * E_];                 // x @ Wx^T + fc_b
__device__ float g_mh[C_ * E_];                 // mem @ Wm^T
__device__ float g_seen_part[8 * B_ * CPAD];    // e-split partials of logits
__device__ float g_logits[B_ * NC_];
__device__ float g_u_part[8 * B_ * P_];         // split-K partials of u
__device__ float g_un[B_ * P_];                 // normalized u
__device__ float g_sqn[B_];                     // ||un||^2 (post-normalize, ref-exact)
__device__ float g_lossrow[B_];
__device__ float g_pp[256 * 4];                 // per-block pair partials

// ------------------------- GEMM: C[m,n] = sum_k A[m,kb+k] * W[n,koff+kb+k] ----
// BM=BN=64, BK=16, 256 threads, 4x4 micro-tile. Split-K via blockIdx.z.
template <bool RELU_A>
__global__ __launch_bounds__(256) void gemm_nt(
    const float* __restrict__ A, int M, int lda,
    const float* __restrict__ W, int ldw, int koff,
    int klen, const float* __restrict__ bias,
    float* __restrict__ Cout, int ldc, long long zstride)
{
    __shared__ float As[16][68];
    __shared__ float Ws[16][68];
    const int t  = threadIdx.x;
    const int tx = t & 15, ty = t >> 4;
    const int m0 = blockIdx.x * 64, n0 = blockIdx.y * 64;
    const int kbase = blockIdx.z * klen;
    const int lr = t >> 2;
    const int lc = (t & 3) * 4;

    float acc[4][4];
#pragma unroll
    for (int i = 0; i < 4; i++)
#pragma unroll
        for (int j = 0; j < 4; j++) acc[i][j] = 0.f;

    for (int kt = 0; kt < klen; kt += 16) {
        float4 av = make_float4(0.f, 0.f, 0.f, 0.f);
        const int am = m0 + lr;
        if (am < M) av = *(const float4*)(A + (long long)am * lda + kbase + kt + lc);
        if (RELU_A) {
            av.x = fmaxf(av.x, 0.f); av.y = fmaxf(av.y, 0.f);
            av.z = fmaxf(av.z, 0.f); av.w = fmaxf(av.w, 0.f);
        }
        const float4 wv = *(const float4*)(W + (long long)(n0 + lr) * ldw + koff + kbase + kt + lc);

        __syncthreads();
        As[lc + 0][lr] = av.x; As[lc + 1][lr] = av.y;
        As[lc + 2][lr] = av.z; As[lc + 3][lr] = av.w;
        Ws[lc + 0][lr] = wv.x; Ws[lc + 1][lr] = wv.y;
        Ws[lc + 2][lr] = wv.z; Ws[lc + 3][lr] = wv.w;
        __syncthreads();

#pragma unroll
        for (int kk = 0; kk < 16; kk++) {
            const float4 a = *(const float4*)&As[kk][ty * 4];
            const float4 b = *(const float4*)&Ws[kk][tx * 4];
            const float aa[4] = {a.x, a.y, a.z, a.w};
            const float bb[4] = {b.x, b.y, b.z, b.w};
#pragma unroll
            for (int i = 0; i < 4; i++)
#pragma unroll
                for (int j = 0; j < 4; j++) acc[i][j] = fmaf(aa[i], bb[j], acc[i][j]);
        }
    }

    float* outp = Cout + (long long)blockIdx.z * zstride;
#pragma unroll
    for (int i = 0; i < 4; i++) {
        const int m = m0 + ty * 4 + i;
        if (m >= M) continue;
#pragma unroll
        for (int j = 0; j < 4; j++) {
            const int n = n0 + tx * 4 + j;
            float v = acc[i][j];
            if (bias != nullptr) v += bias[n];
            outp[(long long)m * ldc + n] = v;
        }
    }
}

// ------------------------- seen/unseen fused -------------------------
// part[z][b][c] = sum_{e in z-chunk} relu(xh[b,e] + mh_ext[c,e]) * p1w[e]
// mh_ext[c] = g_mh row c for c<150, zeros for c>=150 (class 150 == "unseen").
// Block: 64 b-rows x 160 c-cols, blockIdx.y = e-split (8 x 192).
__global__ __launch_bounds__(256) void seen_kernel(const float* __restrict__ p1w)
{
    __shared__ float As[32][68];    // [e][b]
    __shared__ float Ms[32][161];   // [e][c]
    __shared__ float Wsh[32];

    const int t  = threadIdx.x;
    const int tx = t & 31;          // c lane
    const int ty = t >> 5;          // b group (0..7)
    const int b0 = blockIdx.x * 64;
    const int z  = blockIdx.y;      // 0..7
    const int e0 = z * 192;

    float acc[8][5];
#pragma unroll
    for (int i = 0; i < 8; i++)
#pragma unroll
        for (int j = 0; j < 5; j++) acc[i][j] = 0.f;

    for (int ch = 0; ch < 6; ch++) {
        const int ec = e0 + ch * 32;
        __syncthreads();
        // xh tile: 64 x 32  (512 float4)
        for (int idx = t; idx < 512; idx += 256) {
            const int row = idx >> 3;
            const int c4  = idx & 7;
            const float4 v = *(const float4*)(g_xh + (long long)(b0 + row) * E_ + ec + c4 * 4);
            As[c4 * 4 + 0][row] = v.x; As[c4 * 4 + 1][row] = v.y;
            As[c4 * 4 + 2][row] = v.z; As[c4 * 4 + 3][row] = v.w;
        }
        // mh tile: 160 x 32 (1280 float4), rows >= 150 are zero
        for (int idx = t; idx < 1280; idx += 256) {
            const int c  = idx >> 3;
            const int c4 = idx & 7;
            float4 v = make_float4(0.f, 0.f, 0.f, 0.f);
            if (c < C_) v = *(const float4*)(g_mh + (long long)c * E_ + ec + c4 * 4);
            Ms[c4 * 4 + 0][c] = v.x; Ms[c4 * 4 + 1][c] = v.y;
            Ms[c4 * 4 + 2][c] = v.z; Ms[c4 * 4 + 3][c] = v.w;
        }
        if (t < 32) Wsh[t] = p1w[ec + t];
        __syncthreads();

#pragma unroll 4
        for (int e = 0; e < 32; e++) {
            const float w = Wsh[e];
            float a[8];
            const float4 a0 = *(const float4*)&As[e][ty * 8];
            const float4 a1 = *(const float4*)&As[e][ty * 8 + 4];
            a[0] = a0.x; a[1] = a0.y; a[2] = a0.z; a[3] = a0.w;
            a[4] = a1.x; a[5] = a1.y; a[6] = a1.z; a[7] = a1.w;
            float m[5];
#pragma unroll
            for (int j = 0; j < 5; j++) m[j] = Ms[e][tx + 32 * j];
#pragma unroll
            for (int i = 0; i < 8; i++)
#pragma unroll
                for (int j = 0; j < 5; j++)
                    acc[i][j] = fmaf(fmaxf(a[i] + m[j], 0.f), w, acc[i][j]);
        }
    }

    float* outp = g_seen_part + (long long)z * (B_ * CPAD);
#pragma unroll
    for (int i = 0; i < 8; i++) {
        const int b = b0 + ty * 8 + i;
#pragma unroll
        for (int j = 0; j < 5; j++) {
            const int c = tx + 32 * j;
            outp[(long long)b * CPAD + c] = acc[i][j];
        }
    }
}

// logits[b][c] = sum_z part[z][b][c] + p1_b   (c < 151)
__global__ void logits_reduce(const float* __restrict__ p1b)
{
    const int idx = blockIdx.x * 256 + threadIdx.x;
    if (idx >= B_ * NC_) return;
    const int b = idx / NC_;
    const int c = idx - b * NC_;
    float s = p1b[0];
#pragma unroll
    for (int z = 0; z < 8; z++)
        s += g_seen_part[(long long)z * (B_ * CPAD) + (long long)b * CPAD + c];
    g_logits[idx] = s;
}

__device__ __forceinline__ float warp_max(float v) {
#pragma unroll
    for (int o = 16; o > 0; o >>= 1) v = fmaxf(v, __shfl_xor_sync(0xffffffffu, v, o));
    return v;
}
__device__ __forceinline__ float warp_sum(float v) {
#pragma unroll
    for (int o = 16; o > 0; o >>= 1) v += __shfl_xor_sync(0xffffffffu, v, o);
    return v;
}

// per-row masked-softmax losses: g_lossrow[b] = loss1 + loss2
__global__ __launch_bounds__(256) void rowloss_kernel(const int* __restrict__ lb)
{
    const int warp = threadIdx.x >> 5;
    const int lane = threadIdx.x & 31;
    const int b = blockIdx.x * 8 + warp;
    if (b >= B_) return;
    const int label = lb[b];
    const float* row = g_logits + (long long)b * NC_;

    // loss2: allowed = all cols except `label` (all cols if label==150)
    float vmax = -3.0e38f;
    float vals[5];
#pragma unroll
    for (int it = 0; it < 5; it++) {
        const int c = lane + 32 * it;
        float v = -3.0e38f;
        if (c < NC_ && !(label < C_ && c == label)) v = row[c];
        vals[it] = v;
        vmax = fmaxf(vmax, v);
    }
    const float m2 = warp_max(vmax);
    float s = 0.f;
#pragma unroll
    for (int it = 0; it < 5; it++)
        if (vals[it] > -1.0e38f) s += expf(vals[it] - m2);
    const float s2 = warp_sum(s);

    if (lane == 0) {
        const float l150 = row[NC_ - 1];
        const float loss2 = -(l150 - (m2 + logf(s2)));
        float loss1 = 0.f;
        if (label < C_) {
            const float a = row[label];
            const float mm = fmaxf(a, l150);
            const float ss = expf(a - mm) + expf(l150 - mm);
            loss1 = -(a - (mm + logf(ss)));
        }
        g_lossrow[b] = loss1 + loss2;
    }
}

// finalize u: sum split-K partials + bias, L2-normalize rows, store ||un||^2
__global__ __launch_bounds__(256) void u_final_kernel(const float* __restrict__ p2b)
{
    const int warp = threadIdx.x >> 5;
    const int lane = threadIdx.x & 31;
    const int b = blockIdx.x * 8 + warp;
    if (b >= B_) return;

    float v0 = p2b[lane], v1 = p2b[lane + 32];
#pragma unroll
    for (int z = 0; z < 8; z++) {
        const float* p = g_u_part + (long long)z * (B_ * P_) + (long long)b * P_;
        v0 += p[lane];
        v1 += p[lane + 32];
    }
    const float n2 = warp_sum(v0 * v0 + v1 * v1);
    const float n = fmaxf(sqrtf(n2), 1e-12f);
    const float u0 = v0 / n, u1 = v1 / n;
    g_un[(long long)b * P_ + lane]      = u0;
    g_un[(long long)b * P_ + lane + 32] = u1;
    const float sq = warp_sum(u0 * u0 + u1 * u1);
    if (lane == 0) g_sqn[b] = sq;
}

// pairwise contrastive terms: 64x64 pair tile per block, full K=64 dot
__global__ __launch_bounds__(256) void pairs_kernel(const int* __restrict__ lb)
{
    __shared__ float Ui[64][68];   // [k][i]
    __shared__ float Uj[64][68];   // [k][j]
    __shared__ int   lbi[64], lbj[64];
    __shared__ float sqi[64], sqj[64];
    __shared__ float red[8][4];

    const int t  = threadIdx.x;
    const int tx = t & 15, ty = t >> 4;
    const int i0 = blockIdx.x * 64, j0 = blockIdx.y * 64;

    for (int idx = t; idx < 1024; idx += 256) {
        const int row = idx >> 4, c4 = idx & 15;
        float4 v = *(const float4*)(g_un + (long long)(i0 + row) * P_ + c4 * 4);
        Ui[c4 * 4 + 0][row] = v.x; Ui[c4 * 4 + 1][row] = v.y;
        Ui[c4 * 4 + 2][row] = v.z; Ui[c4 * 4 + 3][row] = v.w;
        v = *(const float4*)(g_un + (long long)(j0 + row) * P_ + c4 * 4);
        Uj[c4 * 4 + 0][row] = v.x; Uj[c4 * 4 + 1][row] = v.y;
        Uj[c4 * 4 + 2][row] = v.z; Uj[c4 * 4 + 3][row] = v.w;
    }
    if (t < 64)            { lbi[t] = lb[i0 + t];       sqi[t] = g_sqn[i0 + t]; }
    else if (t < 128)      { lbj[t - 64] = lb[j0 + t - 64]; sqj[t - 64] = g_sqn[j0 + t - 64]; }
    __syncthreads();

    float dot[4][4];
#pragma unroll
    for (int i = 0; i < 4; i++)
#pragma unroll
        for (int j = 0; j < 4; j++) dot[i][j] = 0.f;

#pragma unroll 8
    for (int kk = 0; kk < 64; kk++) {
        const float4 a = *(const float4*)&Ui[kk][ty * 4];
        const float4 b = *(const float4*)&Uj[kk][tx * 4];
        const float aa[4] = {a.x, a.y, a.z, a.w};
        const float bb[4] = {b.x, b.y, b.z, b.w};
#pragma unroll
        for (int i = 0; i < 4; i++)
#pragma unroll
            for (int j = 0; j < 4; j++) dot[i][j] = fmaf(aa[i], bb[j], dot[i][j]);
    }

    float ps = 0.f, pc = 0.f, ns = 0.f, nc = 0.f;
#pragma unroll
    for (int i = 0; i < 4; i++) {
        const int li = ty * 4 + i;
#pragma unroll
        for (int j = 0; j < 4; j++) {
            const int ljj = tx * 4 + j;
            const float sq = sqi[li] + sqj[ljj] - 2.f * dot[i][j];
            const float d = (sq > 0.f) ? sqrtf(fmaxf(sq, 1e-16f)) : 0.f;
            const bool same = (lbi[li] == lbj[ljj]);
            if (same) {
                if ((i0 + li) != (j0 + ljj)) { ps += fmaxf(d - 0.7f, 0.f); pc += 1.f; }
            } else {
                ns += fmaxf(1.4f - d, 0.f); nc += 1.f;
            }
        }
    }
    ps = warp_sum(ps); pc = warp_sum(pc); ns = warp_sum(ns); nc = warp_sum(nc);
    const int warp = t >> 5, lane = t & 31;
    if (lane == 0) { red[warp][0] = ps; red[warp][1] = pc; red[warp][2] = ns; red[warp][3] = nc; }
    __syncthreads();
    if (t == 0) {
        float a0 = 0.f, a1 = 0.f, a2 = 0.f, a3 = 0.f;
#pragma unroll
        for (int w = 0; w < 8; w++) { a0 += red[w][0]; a1 += red[w][1]; a2 += red[w][2]; a3 += red[w][3]; }
        const int bid = blockIdx.y * 16 + blockIdx.x;
        g_pp[bid * 4 + 0] = a0; g_pp[bid * 4 + 1] = a1;
        g_pp[bid * 4 + 2] = a2; g_pp[bid * 4 + 3] = a3;
    }
}

__global__ __launch_bounds__(256) void final_kernel(float* __restrict__ out)
{
    __shared__ float sL[256], sPs[256], sPc[256], sNs[256], sNc[256];
    const int t = threadIdx.x;
    float l = g_lossrow[t] + g_lossrow[t + 256] + g_lossrow[t + 512] + g_lossrow[t + 768];
    sL[t]  = l;
    sPs[t] = g_pp[t * 4 + 0];
    sPc[t] = g_pp[t * 4 + 1];
    sNs[t] = g_pp[t * 4 + 2];
    sNc[t] = g_pp[t * 4 + 3];
    __syncthreads();
    for (int s = 128; s > 0; s >>= 1) {
        if (t < s) {
            sL[t] += sL[t + s]; sPs[t] += sPs[t + s]; sPc[t] += sPc[t + s];
            sNs[t] += sNs[t + s]; sNc[t] += sNc[t + s];
        }
        __syncthreads();
    }
    if (t == 0) {
        const float loss_cls = sL[0] / (float)B_;
        const float pos_l = sPs[0] / fmaxf(sPc[0], 1.f);
        const float neg_l = sNs[0] / fmaxf(sNc[0], 1.f);
        out[0] = loss_cls + pos_l + neg_l;
    }
}

// ------------------------- launch -------------------------
extern "C" void kernel_launch(void* const* d_in, const int* in_sizes, int n_in,
                              void* d_out, int out_size)
{
    const float* x    = (const float*)d_in[0];
    const int*   lb   = (const int*)  d_in[1];
    const float* mem  = (const float*)d_in[2];
    const float* fc_w = (const float*)d_in[3];
    const float* fc_b = (const float*)d_in[4];
    const float* p1_w = (const float*)d_in[5];
    const float* p1_b = (const float*)d_in[6];
    const float* p2_w = (const float*)d_in[7];
    const float* p2_b = (const float*)d_in[8];

    void *pxh = nullptr, *pup = nullptr;
    cudaGetSymbolAddress(&pxh, g_xh);
    cudaGetSymbolAddress(&pup, g_u_part);
    float* xh_ptr = (float*)pxh;
    float* up_ptr = (float*)pup;

    // xh = x @ Wx^T + fc_b      (1024 x 1536, K=768)
    gemm_nt<false><<<dim3(16, 24, 1), 256>>>(x, B_, D_, fc_w, E_, 0, D_, fc_b,
                                             xh_ptr, E_, 0);
    // mh = mem @ Wm^T           (150 x 1536, K=768)
    {
        void* pmh = nullptr; cudaGetSymbolAddress(&pmh, g_mh);
        gemm_nt<false><<<dim3(3, 24, 1), 256>>>(mem, C_, D_, fc_w, E_, D_, D_, nullptr,
                                                (float*)pmh, E_, 0);
    }
    // fused seen+unseen logits partials, e-split x8
    seen_kernel<<<dim3(16, 8, 1), 256>>>(p1_w);
    logits_reduce<<<(B_ * NC_ + 255) / 256, 256>>>(p1_b);
    rowloss_kernel<<<128, 256>>>(lb);
    // u = relu(xh) @ p2_w^T, split-K x8 (K chunk 192)
    gemm_nt<true><<<dim3(16, 1, 8), 256>>>(xh_ptr, B_, E_, p2_w, E_, 0, 192, nullptr,
                                           up_ptr, P_, (long long)B_ * P_);
    u_final_kernel<<<128, 256>>>(p2_b);
    pairs_kernel<<<dim3(16, 16, 1), 256>>>(lb);
    final_kernel<<<1, 256>>>((float*)d_out);
}

// round 6
// speedup vs baseline: 1.1080x; 1.1080x over previous
#include <cuda_runtime.h>
#include <math.h>

#define B_   1024
#define D_   768
#define E_   1536
#define C_   150
#define P_   64
#define CPAD 160
#define NC_  151

typedef unsigned long long ull;

// ------------------------- f32x2 packed-math helpers -------------------------
__device__ __forceinline__ ull pack2(float x, float y) {
    ull r; asm("mov.b64 %0, {%1,%2};" : "=l"(r) : "f"(x), "f"(y)); return r;
}
__device__ __forceinline__ void unpack2(ull v, float& x, float& y) {
    asm("mov.b64 {%0,%1}, %2;" : "=f"(x), "=f"(y) : "l"(v));
}
__device__ __forceinline__ ull ffma2(ull a, ull b, ull c) {
    ull d; asm("fma.rn.f32x2 %0, %1, %2, %3;" : "=l"(d) : "l"(a), "l"(b), "l"(c)); return d;
}

// ------------------------- static device scratch -------------------------
__device__ float g_xh[B_ * E_];                 // x @ Wx^T + fc_b
__device__ float g_mh[C_ * E_];                 // mem @ Wm^T
__device__ float g_seen_part[8 * B_ * CPAD];    // e-split partials of logits
__device__ float g_u_part[8 * B_ * P_];         // split-K partials of u
__device__ float g_un[B_ * P_];                 // normalized u
__device__ float g_sqn[B_];                     // ||un||^2 (post-normalize)
__device__ float g_lossrow[B_];
__device__ float g_pp[256 * 4];                 // per-block pair partials

// ------------------------- f32x2 GEMM core -------------------------
// C[m0+i, n0+j] = sum_{k} A[m0+i, kbase+k] * W[n0+j, koff+kbase+k]  (+bias[n])
// 64 threads, 64x64 tile, 8x8 micro-tile, BK=16, FFMA2 inner product.
template <bool RELU_A>
__device__ __forceinline__ void gemm_core(
    const float* __restrict__ A, int M, int m0, int lda,
    const float* __restrict__ W, int n0, int ldw, int koff,
    int kbase, int klen, const float* __restrict__ bias,
    float* __restrict__ out, int ldc)
{
    __shared__ float As[16][72];
    __shared__ float Ws[16][72];
    const int t  = threadIdx.x;       // 0..63
    const int tx = t & 7;             // n group
    const int ty = t >> 3;            // m group

    ull acc[8][4];
#pragma unroll
    for (int i = 0; i < 8; i++)
#pragma unroll
        for (int j = 0; j < 4; j++) acc[i][j] = 0ull;

    for (int kt = 0; kt < klen; kt += 16) {
        __syncthreads();
#pragma unroll
        for (int l = 0; l < 4; l++) {
            const int idx = t + 64 * l;        // 0..255
            const int row = idx >> 2;          // 0..63
            const int q   = idx & 3;           // float4 within row
            float4 av = make_float4(0.f, 0.f, 0.f, 0.f);
            const int am = m0 + row;
            if (am < M) av = *(const float4*)(A + (long long)am * lda + kbase + kt + q * 4);
            if (RELU_A) {
                av.x = fmaxf(av.x, 0.f); av.y = fmaxf(av.y, 0.f);
                av.z = fmaxf(av.z, 0.f); av.w = fmaxf(av.w, 0.f);
            }
            As[q * 4 + 0][row] = av.x; As[q * 4 + 1][row] = av.y;
            As[q * 4 + 2][row] = av.z; As[q * 4 + 3][row] = av.w;
            const float4 wv = *(const float4*)(W + (long long)(n0 + row) * ldw + koff + kbase + kt + q * 4);
            Ws[q * 4 + 0][row] = wv.x; Ws[q * 4 + 1][row] = wv.y;
            Ws[q * 4 + 2][row] = wv.z; Ws[q * 4 + 3][row] = wv.w;
        }
        __syncthreads();

#pragma unroll 8
        for (int kk = 0; kk < 16; kk++) {
            const float4 a0 = *(const float4*)&As[kk][ty * 8];
            const float4 a1 = *(const float4*)&As[kk][ty * 8 + 4];
            const float4 b0 = *(const float4*)&Ws[kk][tx * 8];
            const float4 b1 = *(const float4*)&Ws[kk][tx * 8 + 4];
            const ull bp0 = pack2(b0.x, b0.y);
            const ull bp1 = pack2(b0.z, b0.w);
            const ull bp2 = pack2(b1.x, b1.y);
            const ull bp3 = pack2(b1.z, b1.w);
            const float aa[8] = {a0.x, a0.y, a0.z, a0.w, a1.x, a1.y, a1.z, a1.w};
#pragma unroll
            for (int i = 0; i < 8; i++) {
                const ull ai = pack2(aa[i], aa[i]);
                acc[i][0] = ffma2(ai, bp0, acc[i][0]);
                acc[i][1] = ffma2(ai, bp1, acc[i][1]);
                acc[i][2] = ffma2(ai, bp2, acc[i][2]);
                acc[i][3] = ffma2(ai, bp3, acc[i][3]);
            }
        }
    }

    const int nb = n0 + tx * 8;
    float bv[8];
#pragma unroll
    for (int q = 0; q < 8; q++) bv[q] = (bias != nullptr) ? bias[nb + q] : 0.f;
#pragma unroll
    for (int i = 0; i < 8; i++) {
        const int m = m0 + ty * 8 + i;
        if (m >= M) continue;
        float o[8];
#pragma unroll
        for (int jp = 0; jp < 4; jp++) unpack2(acc[i][jp], o[2 * jp], o[2 * jp + 1]);
#pragma unroll
        for (int q = 0; q < 8; q++) o[q] += bv[q];
        *(float4*)(out + (long long)m * ldc + nb)     = make_float4(o[0], o[1], o[2], o[3]);
        *(float4*)(out + (long long)m * ldc + nb + 4) = make_float4(o[4], o[5], o[6], o[7]);
    }
}

// combined xh (bx<16) and mh (bx>=16) launch
__global__ __launch_bounds__(64) void gemm_xhmh(
    const float* __restrict__ x, const float* __restrict__ mem,
    const float* __restrict__ fc_w, const float* __restrict__ fc_b,
    float* __restrict__ xh, float* __restrict__ mh)
{
    const int bx = blockIdx.x;
    const int n0 = blockIdx.y * 64;
    const float* A; int M, m0, koff; const float* bias; float* out;
    if (bx < 16) { A = x;   M = B_; m0 = bx * 64;        koff = 0;  bias = fc_b;   out = xh; }
    else         { A = mem; M = C_; m0 = (bx - 16) * 64; koff = D_; bias = nullptr; out = mh; }
    gemm_core<false>(A, M, m0, D_, fc_w, n0, E_, koff, 0, D_, bias, out, E_);
}

// u partials: relu(xh) @ p2_w^T, split-K = 8 (chunks of 192)
__global__ __launch_bounds__(64) void gemm_u(
    const float* __restrict__ xh, const float* __restrict__ p2w,
    float* __restrict__ outbase)
{
    const int z = blockIdx.z;
    gemm_core<true>(xh, B_, blockIdx.x * 64, E_, p2w, 0, E_, 0,
                    z * 192, 192, nullptr, outbase + (long long)z * (B_ * P_), P_);
}

// ------------------------- seen/unseen fused -------------------------
// part[z][b][c] = sum_{e in z-chunk} relu(xh[b,e] + mh_ext[c,e]) * p1w[e]
// class 150 == "unseen" (mh row = 0). Block: 64 b x 160 c; blockIdx.y = e-split.
__global__ __launch_bounds__(256) void seen_kernel(const float* __restrict__ p1w)
{
    __shared__ float As[32][68];    // [e][b]
    __shared__ float Ms[32][161];   // [e][c]
    __shared__ float Wsh[32];

    const int t  = threadIdx.x;
    const int tx = t & 31;          // c lane
    const int ty = t >> 5;          // b group (0..7)
    const int b0 = blockIdx.x * 64;
    const int z  = blockIdx.y;      // 0..7
    const int e0 = z * 192;

    ull acc[4][5];
#pragma unroll
    for (int p = 0; p < 4; p++)
#pragma unroll
        for (int j = 0; j < 5; j++) acc[p][j] = 0ull;

    for (int ch = 0; ch < 6; ch++) {
        const int ec = e0 + ch * 32;
        __syncthreads();
        for (int idx = t; idx < 512; idx += 256) {
            const int row = idx >> 3;
            const int c4  = idx & 7;
            const float4 v = *(const float4*)(g_xh + (long long)(b0 + row) * E_ + ec + c4 * 4);
            As[c4 * 4 + 0][row] = v.x; As[c4 * 4 + 1][row] = v.y;
            As[c4 * 4 + 2][row] = v.z; As[c4 * 4 + 3][row] = v.w;
        }
        for (int idx = t; idx < 1280; idx += 256) {
            const int c  = idx >> 3;
            const int c4 = idx & 7;
            float4 v = make_float4(0.f, 0.f, 0.f, 0.f);
            if (c < C_) v = *(const float4*)(g_mh + (long long)c * E_ + ec + c4 * 4);
            Ms[c4 * 4 + 0][c] = v.x; Ms[c4 * 4 + 1][c] = v.y;
            Ms[c4 * 4 + 2][c] = v.z; Ms[c4 * 4 + 3][c] = v.w;
        }
        if (t < 32) Wsh[t] = p1w[ec + t];
        __syncthreads();

#pragma unroll 4
        for (int e = 0; e < 32; e++) {
            const float w = Wsh[e];
            const ull w2 = pack2(w, w);
            const float4 a0 = *(const float4*)&As[e][ty * 8];
            const float4 a1 = *(const float4*)&As[e][ty * 8 + 4];
            const float aa[8] = {a0.x, a0.y, a0.z, a0.w, a1.x, a1.y, a1.z, a1.w};
#pragma unroll
            for (int j = 0; j < 5; j++) {
                const float m = Ms[e][tx + 32 * j];
#pragma unroll
                for (int p = 0; p < 4; p++) {
                    const float r0 = fmaxf(aa[2 * p]     + m, 0.f);
                    const float r1 = fmaxf(aa[2 * p + 1] + m, 0.f);
                    acc[p][j] = ffma2(pack2(r0, r1), w2, acc[p][j]);
                }
            }
        }
    }

    float* outp = g_seen_part + (long long)z * (B_ * CPAD);
#pragma unroll
    for (int p = 0; p < 4; p++) {
        float f0, f1;
#pragma unroll
        for (int j = 0; j < 5; j++) {
            unpack2(acc[p][j], f0, f1);
            const int c = tx + 32 * j;
            outp[(long long)(b0 + ty * 8 + 2 * p)     * CPAD + c] = f0;
            outp[(long long)(b0 + ty * 8 + 2 * p + 1) * CPAD + c] = f1;
        }
    }
}

// ------------------------- warp reduce helpers -------------------------
__device__ __forceinline__ float warp_max(float v) {
#pragma unroll
    for (int o = 16; o > 0; o >>= 1) v = fmaxf(v, __shfl_xor_sync(0xffffffffu, v, o));
    return v;
}
__device__ __forceinline__ float warp_sum(float v) {
#pragma unroll
    for (int o = 16; o > 0; o >>= 1) v += __shfl_xor_sync(0xffffffffu, v, o);
    return v;
}

// per-row: reduce e-split partials into logits on the fly, then masked-softmax losses
__global__ __launch_bounds__(256) void rowloss_kernel(const int* __restrict__ lb,
                                                      const float* __restrict__ p1b)
{
    const int warp = threadIdx.x >> 5;
    const int lane = threadIdx.x & 31;
    const int b = blockIdx.x * 8 + warp;
    if (b >= B_) return;
    const int label = lb[b];
    const float bias0 = p1b[0];

    // raw logits: lane handles c = lane + 32*it, it<5
    float raw[5];
#pragma unroll
    for (int it = 0; it < 5; it++) {
        const int c = lane + 32 * it;
        float s = bias0;
        if (c < NC_) {
#pragma unroll
            for (int zz = 0; zz < 8; zz++)
                s += g_seen_part[(long long)zz * (B_ * CPAD) + (long long)b * CPAD + c];
            raw[it] = s;
        } else raw[it] = -3.0e38f;
    }

    const float l150 = __shfl_sync(0xffffffffu, raw[4], NC_ - 1 - 128);  // c=150 -> lane 22, it 4
    float lv = -3.0e38f;
#pragma unroll
    for (int it = 0; it < 5; it++)
        if (lane + 32 * it == label) lv = raw[it];
    lv = warp_max(lv);

    // loss2: all classes except `label` (all if label == C_)
    float vmax = -3.0e38f;
    float ex[5];
#pragma unroll
    for (int it = 0; it < 5; it++) {
        float v = raw[it];
        if (label < C_ && (lane + 32 * it) == label) v = -3.0e38f;
        ex[it] = v;
        vmax = fmaxf(vmax, v);
    }
    const float m2 = warp_max(vmax);
    float s = 0.f;
#pragma unroll
    for (int it = 0; it < 5; it++)
        if (ex[it] > -1.0e38f) s += expf(ex[it] - m2);
    const float s2 = warp_sum(s);

    if (lane == 0) {
        const float loss2 = -(l150 - (m2 + logf(s2)));
        float loss1 = 0.f;
        if (label < C_) {
            const float mm = fmaxf(lv, l150);
            const float ss = expf(lv - mm) + expf(l150 - mm);
            loss1 = -(lv - (mm + logf(ss)));
        }
        g_lossrow[b] = loss1 + loss2;
    }
}

// finalize u: sum split-K partials + bias, L2-normalize, store ||un||^2
__global__ __launch_bounds__(256) void u_final_kernel(const float* __restrict__ p2b)
{
    const int warp = threadIdx.x >> 5;
    const int lane = threadIdx.x & 31;
    const int b = blockIdx.x * 8 + warp;
    if (b >= B_) return;

    float v0 = p2b[lane], v1 = p2b[lane + 32];
#pragma unroll
    for (int z = 0; z < 8; z++) {
        const float* p = g_u_part + (long long)z * (B_ * P_) + (long long)b * P_;
        v0 += p[lane];
        v1 += p[lane + 32];
    }
    const float n2 = warp_sum(v0 * v0 + v1 * v1);
    const float n = fmaxf(sqrtf(n2), 1e-12f);
    const float u0 = v0 / n, u1 = v1 / n;
    g_un[(long long)b * P_ + lane]      = u0;
    g_un[(long long)b * P_ + lane + 32] = u1;
    const float sq = warp_sum(u0 * u0 + u1 * u1);
    if (lane == 0) g_sqn[b] = sq;
}

// pairwise contrastive terms: 64x64 pair tile / block, K=64 dots via FFMA2
__global__ __launch_bounds__(256) void pairs_kernel(const int* __restrict__ lb)
{
    __shared__ float Ui[64][68];
    __shared__ float Uj[64][68];
    __shared__ int   lbi[64], lbj[64];
    __shared__ float sqi[64], sqj[64];
    __shared__ float red[8][4];

    const int t  = threadIdx.x;
    const int tx = t & 15, ty = t >> 4;
    const int i0 = blockIdx.x * 64, j0 = blockIdx.y * 64;

    for (int idx = t; idx < 1024; idx += 256) {
        const int row = idx >> 4, c4 = idx & 15;
        float4 v = *(const float4*)(g_un + (long long)(i0 + row) * P_ + c4 * 4);
        Ui[c4 * 4 + 0][row] = v.x; Ui[c4 * 4 + 1][row] = v.y;
        Ui[c4 * 4 + 2][row] = v.z; Ui[c4 * 4 + 3][row] = v.w;
        v = *(const float4*)(g_un + (long long)(j0 + row) * P_ + c4 * 4);
        Uj[c4 * 4 + 0][row] = v.x; Uj[c4 * 4 + 1][row] = v.y;
        Uj[c4 * 4 + 2][row] = v.z; Uj[c4 * 4 + 3][row] = v.w;
    }
    if (t < 64)       { lbi[t] = lb[i0 + t];           sqi[t] = g_sqn[i0 + t]; }
    else if (t < 128) { lbj[t - 64] = lb[j0 + t - 64]; sqj[t - 64] = g_sqn[j0 + t - 64]; }
    __syncthreads();

    ull dot2[4][2];
#pragma unroll
    for (int i = 0; i < 4; i++) { dot2[i][0] = 0ull; dot2[i][1] = 0ull; }

#pragma unroll 8
    for (int kk = 0; kk < 64; kk++) {
        const float4 a = *(const float4*)&Ui[kk][ty * 4];
        const float4 b = *(const float4*)&Uj[kk][tx * 4];
        const ull b01 = pack2(b.x, b.y);
        const ull b23 = pack2(b.z, b.w);
        const float aa[4] = {a.x, a.y, a.z, a.w};
#pragma unroll
        for (int i = 0; i < 4; i++) {
            const ull ai = pack2(aa[i], aa[i]);
            dot2[i][0] = ffma2(ai, b01, dot2[i][0]);
            dot2[i][1] = ffma2(ai, b23, dot2[i][1]);
        }
    }

    float ps = 0.f, pc = 0.f, ns = 0.f, nc = 0.f;
#pragma unroll
    for (int i = 0; i < 4; i++) {
        const int li = ty * 4 + i;
        float dd[4];
        unpack2(dot2[i][0], dd[0], dd[1]);
        unpack2(dot2[i][1], dd[2], dd[3]);
#pragma unroll
        for (int j = 0; j < 4; j++) {
            const int ljj = tx * 4 + j;
            const float sq = sqi[li] + sqj[ljj] - 2.f * dd[j];
            const float d = (sq > 0.f) ? sqrtf(fmaxf(sq, 1e-16f)) : 0.f;
            if (lbi[li] == lbj[ljj]) {
                if ((i0 + li) != (j0 + ljj)) { ps += fmaxf(d - 0.7f, 0.f); pc += 1.f; }
            } else {
                ns += fmaxf(1.4f - d, 0.f); nc += 1.f;
            }
        }
    }
    ps = warp_sum(ps); pc = warp_sum(pc); ns = warp_sum(ns); nc = warp_sum(nc);
    const int warp = t >> 5, lane = t & 31;
    if (lane == 0) { red[warp][0] = ps; red[warp][1] = pc; red[warp][2] = ns; red[warp][3] = nc; }
    __syncthreads();
    if (t == 0) {
        float a0 = 0.f, a1 = 0.f, a2 = 0.f, a3 = 0.f;
#pragma unroll
        for (int w = 0; w < 8; w++) { a0 += red[w][0]; a1 += red[w][1]; a2 += red[w][2]; a3 += red[w][3]; }
        const int bid = blockIdx.y * 16 + blockIdx.x;
        g_pp[bid * 4 + 0] = a0; g_pp[bid * 4 + 1] = a1;
        g_pp[bid * 4 + 2] = a2; g_pp[bid * 4 + 3] = a3;
    }
}

__global__ __launch_bounds__(256) void final_kernel(float* __restrict__ out)
{
    __shared__ float sL[256], sPs[256], sPc[256], sNs[256], sNc[256];
    const int t = threadIdx.x;
    sL[t]  = g_lossrow[t] + g_lossrow[t + 256] + g_lossrow[t + 512] + g_lossrow[t + 768];
    sPs[t] = g_pp[t * 4 + 0];
    sPc[t] = g_pp[t * 4 + 1];
    sNs[t] = g_pp[t * 4 + 2];
    sNc[t] = g_pp[t * 4 + 3];
    __syncthreads();
    for (int s = 128; s > 0; s >>= 1) {
        if (t < s) {
            sL[t] += sL[t + s]; sPs[t] += sPs[t + s]; sPc[t] += sPc[t + s];
            sNs[t] += sNs[t + s]; sNc[t] += sNc[t + s];
        }
        __syncthreads();
    }
    if (t == 0) {
        const float loss_cls = sL[0] / (float)B_;
        const float pos_l = sPs[0] / fmaxf(sPc[0], 1.f);
        const float neg_l = sNs[0] / fmaxf(sNc[0], 1.f);
        out[0] = loss_cls + pos_l + neg_l;
    }
}

// ------------------------- launch -------------------------
extern "C" void kernel_launch(void* const* d_in, const int* in_sizes, int n_in,
                              void* d_out, int out_size)
{
    const float* x    = (const float*)d_in[0];
    const int*   lb   = (const int*)  d_in[1];
    const float* mem  = (const float*)d_in[2];
    const float* fc_w = (const float*)d_in[3];
    const float* fc_b = (const float*)d_in[4];
    const float* p1_w = (const float*)d_in[5];
    const float* p1_b = (const float*)d_in[6];
    const float* p2_w = (const float*)d_in[7];
    const float* p2_b = (const float*)d_in[8];

    void *pxh = nullptr, *pmh = nullptr, *pup = nullptr;
    cudaGetSymbolAddress(&pxh, g_xh);
    cudaGetSymbolAddress(&pmh, g_mh);
    cudaGetSymbolAddress(&pup, g_u_part);

    gemm_xhmh<<<dim3(19, 24, 1), 64>>>(x, mem, fc_w, fc_b, (float*)pxh, (float*)pmh);
    gemm_u<<<dim3(16, 1, 8), 64>>>((const float*)pxh, p2_w, (float*)pup);
    seen_kernel<<<dim3(16, 8, 1), 256>>>(p1_w);
    rowloss_kernel<<<128, 256>>>(lb, p1_b);
    u_final_kernel<<<128, 256>>>(p2_b);
    pairs_kernel<<<dim3(16, 16, 1), 256>>>(lb);
    final_kernel<<<1, 256>>>((float*)d_out);
}